// round 2
// baseline (speedup 1.0000x reference)
#include <cuda_runtime.h>
#include <math.h>
#include <stdint.h>

// ---------------------------------------------------------------------------
// GraphProjection: 80000 points, 3 cameras, feature pyramid (64/128/256/512 ch)
// out[p] = [coord(3) | max over views(960) | mean(960) | std(960)] -> 2883 f32
// Round 2: fused to 2 launches; LDG.128 gather (4 channels/thread).
// ---------------------------------------------------------------------------

#define MAX_N 80000
#define OUT_STRIDE 2883

__device__ int g_off[MAX_N * 12];   // [point][view*4 + scale] flat float offset

struct CamData {
    float B0[9];     // inv(c0^T)
    float c[3][9];   // per-view rotation rows (X,Y,Z normalized)
    float o[3][3];   // per-view camera origin (unnormalized Z)
};

// --- camera matrix, mirroring jnp fp32 op order -----------------------------
__device__ __forceinline__ void cam_mat(const float* prm, float* Crow, float* O) {
    const float PI = 3.14159265358979323846f;
    float theta = prm[0] * PI / 180.0f;
    float e     = prm[1] * PI / 180.0f;
    float camy  = prm[3] * sinf(e);
    float lens  = prm[3] * cosf(e);
    float camx  = lens * cosf(theta);
    float camz  = lens * sinf(theta);

    float Zv[3] = { camx, camy, camz };
    float Yv[3] = { camy * cosf(theta + PI), lens, camy * sinf(theta + PI) };
    float Xv[3] = { Yv[1]*Zv[2] - Yv[2]*Zv[1],
                    Yv[2]*Zv[0] - Yv[0]*Zv[2],
                    Yv[0]*Zv[1] - Yv[1]*Zv[0] };

    float nx = sqrtf(Xv[0]*Xv[0] + Xv[1]*Xv[1] + Xv[2]*Xv[2]);
    float ny = sqrtf(Yv[0]*Yv[0] + Yv[1]*Yv[1] + Yv[2]*Yv[2]);
    float nz = sqrtf(Zv[0]*Zv[0] + Zv[1]*Zv[1] + Zv[2]*Zv[2]);
    for (int k = 0; k < 3; k++) {
        Crow[0*3 + k] = __fdiv_rn(Xv[k], nx);
        Crow[1*3 + k] = __fdiv_rn(Yv[k], ny);
        Crow[2*3 + k] = __fdiv_rn(Zv[k], nz);
        O[k] = Zv[k];
    }
}

// --- kernel A: per-block camera setup (incl. DP inverse) + per-point offsets
__global__ __launch_bounds__(256)
void proj_kernel(const float* __restrict__ coord,
                 const float* __restrict__ cams, int N) {
    __shared__ CamData cam;

    if (threadIdx.x == 0) {
        for (int i = 0; i < 3; i++)
            cam_mat(cams + i * 5, cam.c[i], cam.o[i]);

        // B0 = inv(c0^T), double-precision cofactors of the fp32 matrix.
        double M[3][3];
        for (int r = 0; r < 3; r++)
            for (int k = 0; k < 3; k++)
                M[r][k] = (double)cam.c[0][k*3 + r];

        double det = M[0][0]*(M[1][1]*M[2][2] - M[1][2]*M[2][1])
                   - M[0][1]*(M[1][0]*M[2][2] - M[1][2]*M[2][0])
                   + M[0][2]*(M[1][0]*M[2][1] - M[1][1]*M[2][0]);
        double inv[3][3];
        inv[0][0] =  (M[1][1]*M[2][2] - M[1][2]*M[2][1]) / det;
        inv[0][1] =  (M[0][2]*M[2][1] - M[0][1]*M[2][2]) / det;
        inv[0][2] =  (M[0][1]*M[1][2] - M[0][2]*M[1][1]) / det;
        inv[1][0] =  (M[1][2]*M[2][0] - M[1][0]*M[2][2]) / det;
        inv[1][1] =  (M[0][0]*M[2][2] - M[0][2]*M[2][0]) / det;
        inv[1][2] =  (M[0][2]*M[1][0] - M[0][0]*M[1][2]) / det;
        inv[2][0] =  (M[1][0]*M[2][1] - M[1][1]*M[2][0]) / det;
        inv[2][1] =  (M[0][1]*M[2][0] - M[0][0]*M[2][1]) / det;
        inv[2][2] =  (M[0][0]*M[1][1] - M[0][1]*M[1][0]) / det;
        for (int k = 0; k < 3; k++)
            for (int j = 0; j < 3; j++)
                cam.B0[k*3 + j] = (float)inv[k][j];
    }
    __syncthreads();

    int p = blockIdx.x * blockDim.x + threadIdx.x;
    if (p >= N) return;

    float x = coord[p*3 + 0];
    float y = coord[p*3 + 1];
    float z = coord[p*3 + 2];

    float po[3];
    #pragma unroll
    for (int j = 0; j < 3; j++)
        po[j] = x * cam.B0[0*3 + j] + y * cam.B0[1*3 + j]
              + z * cam.B0[2*3 + j] + cam.o[0][j];

    const int   ds[4] = { 56, 28, 14, 7 };
    const int   Cs[4] = { 64, 128, 256, 512 };
    const float qi[4] = { 0.25f, 0.125f, 0.0625f, 0.03125f };  // d/224 exact pow2

    int off[12];
    #pragma unroll
    for (int i = 0; i < 3; i++) {
        float vx = po[0] - cam.o[i][0];
        float vy = po[1] - cam.o[i][1];
        float vz = po[2] - cam.o[i][2];
        const float* C = cam.c[i];
        float X  = vx*C[0] + vy*C[1] + vz*C[2];
        float Y  = vx*C[3] + vy*C[4] + vz*C[5];
        float Zc = vx*C[6] + vy*C[7] + vz*C[8];

        float negz = -Zc;
        float h = __fdiv_rn(248.0f * (-Y), negz) + 112.0f;
        float w = __fdiv_rn(248.0f * X,    negz) + 112.0f;
        h = fminf(fmaxf(h, 0.0f), 223.0f);
        w = fminf(fmaxf(w, 0.0f), 223.0f);

        #pragma unroll
        for (int s = 0; s < 4; s++) {
            int ih = (int)(h * qi[s]);
            int iw = (int)(w * qi[s]);
            off[i*4 + s] = (ih * ds[s] + iw) * Cs[s];
        }
    }
    // 12 ints = 48B, 16B aligned -> 3x STG.128
    int4* dst = reinterpret_cast<int4*>(g_off + p*12);
    dst[0] = make_int4(off[0], off[1], off[2],  off[3]);
    dst[1] = make_int4(off[4], off[5], off[6],  off[7]);
    dst[2] = make_int4(off[8], off[9], off[10], off[11]);
}

// --- kernel B: gather (float4) + per-channel stats + coord passthrough ------
__global__ __launch_bounds__(256)
void gather_kernel(const float* __restrict__ f1, const float* __restrict__ f2,
                   const float* __restrict__ f3, const float* __restrict__ f4,
                   const float* __restrict__ coord, float* __restrict__ out) {
    int p = blockIdx.x;
    int t = threadIdx.x;

    __shared__ int soff[12];
    if (t < 12) soff[t] = g_off[p*12 + t];
    __syncthreads();

    float* op = out + (size_t)p * OUT_STRIDE;

    if (t < 240) {
        int c4 = t * 4;               // first of 4 consecutive channels
        const float* f;
        int cl, s;
        if (c4 < 64)       { s = 0; f = f1; cl = c4; }
        else if (c4 < 192) { s = 1; f = f2; cl = c4 - 64; }
        else if (c4 < 448) { s = 2; f = f3; cl = c4 - 192; }
        else               { s = 3; f = f4; cl = c4 - 448; }

        float4 a = __ldg(reinterpret_cast<const float4*>(f + soff[0 + s] + cl));
        float4 b = __ldg(reinterpret_cast<const float4*>(f + soff[4 + s] + cl));
        float4 d = __ldg(reinterpret_cast<const float4*>(f + soff[8 + s] + cl));

        float av[4] = { a.x, a.y, a.z, a.w };
        float bv[4] = { b.x, b.y, b.z, b.w };
        float dv[4] = { d.x, d.y, d.z, d.w };

        #pragma unroll
        for (int k = 0; k < 4; k++) {
            float aa = av[k], bb = bv[k], dd = dv[k];
            float mx = fmaxf(aa, fmaxf(bb, dd));
            float mn = (aa + bb + dd) * (1.0f / 3.0f);
            float da = aa - mn, db = bb - mn, dc = dd - mn;
            float sd = sqrtf((da*da + db*db + dc*dc) * (1.0f / 3.0f));
            op[3 + c4 + k]    = mx;
            op[963 + c4 + k]  = mn;
            op[1923 + c4 + k] = sd;
        }
    } else if (t < 243) {
        int k = t - 240;
        op[k] = __ldg(coord + p*3 + k);
    }
}

extern "C" void kernel_launch(void* const* d_in, const int* in_sizes, int n_in,
                              void* d_out, int out_size) {
    const float* coord = (const float*)d_in[0];
    const float* cams  = (const float*)d_in[1];
    const float* f1    = (const float*)d_in[2];
    const float* f2    = (const float*)d_in[3];
    const float* f3    = (const float*)d_in[4];
    const float* f4    = (const float*)d_in[5];
    float* out = (float*)d_out;

    int N = in_sizes[0] / 3;

    proj_kernel<<<(N + 255) / 256, 256>>>(coord, cams, N);
    gather_kernel<<<N, 256>>>(f1, f2, f3, f4, coord, out);
}

// round 3
// speedup vs baseline: 1.6090x; 1.6090x over previous
#include <cuda_runtime.h>
#include <math.h>
#include <stdint.h>

// ---------------------------------------------------------------------------
// GraphProjection: 80000 points, 3 cameras, feature pyramid (64/128/256/512 ch)
// out[p] = [coord(3) | max over views(960) | mean(960) | std(960)] -> 2883 f32
// Round 3: float4 gathers + smem-staged, alignment-fixed, coalesced writeback.
// ---------------------------------------------------------------------------

#define MAX_N 80000
#define OUT_STRIDE 2883

__device__ int g_off[MAX_N * 12];   // [point][view*4 + scale] flat float offset

struct CamData {
    float B0[9];     // inv(c0^T)
    float c[3][9];   // per-view rotation rows (X,Y,Z normalized)
    float o[3][3];   // per-view camera origin (unnormalized Z)
};

// --- camera matrix, mirroring jnp fp32 op order -----------------------------
__device__ __forceinline__ void cam_mat(const float* prm, float* Crow, float* O) {
    const float PI = 3.14159265358979323846f;
    float theta = prm[0] * PI / 180.0f;
    float e     = prm[1] * PI / 180.0f;
    float camy  = prm[3] * sinf(e);
    float lens  = prm[3] * cosf(e);
    float camx  = lens * cosf(theta);
    float camz  = lens * sinf(theta);

    float Zv[3] = { camx, camy, camz };
    float Yv[3] = { camy * cosf(theta + PI), lens, camy * sinf(theta + PI) };
    float Xv[3] = { Yv[1]*Zv[2] - Yv[2]*Zv[1],
                    Yv[2]*Zv[0] - Yv[0]*Zv[2],
                    Yv[0]*Zv[1] - Yv[1]*Zv[0] };

    float nx = sqrtf(Xv[0]*Xv[0] + Xv[1]*Xv[1] + Xv[2]*Xv[2]);
    float ny = sqrtf(Yv[0]*Yv[0] + Yv[1]*Yv[1] + Yv[2]*Yv[2]);
    float nz = sqrtf(Zv[0]*Zv[0] + Zv[1]*Zv[1] + Zv[2]*Zv[2]);
    for (int k = 0; k < 3; k++) {
        Crow[0*3 + k] = __fdiv_rn(Xv[k], nx);
        Crow[1*3 + k] = __fdiv_rn(Yv[k], ny);
        Crow[2*3 + k] = __fdiv_rn(Zv[k], nz);
        O[k] = Zv[k];
    }
}

// --- kernel A: per-block camera setup (incl. DP inverse) + per-point offsets
__global__ __launch_bounds__(256)
void proj_kernel(const float* __restrict__ coord,
                 const float* __restrict__ cams, int N) {
    __shared__ CamData cam;

    if (threadIdx.x == 0) {
        for (int i = 0; i < 3; i++)
            cam_mat(cams + i * 5, cam.c[i], cam.o[i]);

        double M[3][3];
        for (int r = 0; r < 3; r++)
            for (int k = 0; k < 3; k++)
                M[r][k] = (double)cam.c[0][k*3 + r];

        double det = M[0][0]*(M[1][1]*M[2][2] - M[1][2]*M[2][1])
                   - M[0][1]*(M[1][0]*M[2][2] - M[1][2]*M[2][0])
                   + M[0][2]*(M[1][0]*M[2][1] - M[1][1]*M[2][0]);
        double inv[3][3];
        inv[0][0] =  (M[1][1]*M[2][2] - M[1][2]*M[2][1]) / det;
        inv[0][1] =  (M[0][2]*M[2][1] - M[0][1]*M[2][2]) / det;
        inv[0][2] =  (M[0][1]*M[1][2] - M[0][2]*M[1][1]) / det;
        inv[1][0] =  (M[1][2]*M[2][0] - M[1][0]*M[2][2]) / det;
        inv[1][1] =  (M[0][0]*M[2][2] - M[0][2]*M[2][0]) / det;
        inv[1][2] =  (M[0][2]*M[1][0] - M[0][0]*M[1][2]) / det;
        inv[2][0] =  (M[1][0]*M[2][1] - M[1][1]*M[2][0]) / det;
        inv[2][1] =  (M[0][1]*M[2][0] - M[0][0]*M[2][1]) / det;
        inv[2][2] =  (M[0][0]*M[1][1] - M[0][1]*M[1][0]) / det;
        for (int k = 0; k < 3; k++)
            for (int j = 0; j < 3; j++)
                cam.B0[k*3 + j] = (float)inv[k][j];
    }
    __syncthreads();

    int p = blockIdx.x * blockDim.x + threadIdx.x;
    if (p >= N) return;

    float x = coord[p*3 + 0];
    float y = coord[p*3 + 1];
    float z = coord[p*3 + 2];

    float po[3];
    #pragma unroll
    for (int j = 0; j < 3; j++)
        po[j] = x * cam.B0[0*3 + j] + y * cam.B0[1*3 + j]
              + z * cam.B0[2*3 + j] + cam.o[0][j];

    const int   ds[4] = { 56, 28, 14, 7 };
    const int   Cs[4] = { 64, 128, 256, 512 };
    const float qi[4] = { 0.25f, 0.125f, 0.0625f, 0.03125f };  // d/224 exact pow2

    int off[12];
    #pragma unroll
    for (int i = 0; i < 3; i++) {
        float vx = po[0] - cam.o[i][0];
        float vy = po[1] - cam.o[i][1];
        float vz = po[2] - cam.o[i][2];
        const float* C = cam.c[i];
        float X  = vx*C[0] + vy*C[1] + vz*C[2];
        float Y  = vx*C[3] + vy*C[4] + vz*C[5];
        float Zc = vx*C[6] + vy*C[7] + vz*C[8];

        float negz = -Zc;
        float h = __fdiv_rn(248.0f * (-Y), negz) + 112.0f;
        float w = __fdiv_rn(248.0f * X,    negz) + 112.0f;
        h = fminf(fmaxf(h, 0.0f), 223.0f);
        w = fminf(fmaxf(w, 0.0f), 223.0f);

        #pragma unroll
        for (int s = 0; s < 4; s++) {
            int ih = (int)(h * qi[s]);
            int iw = (int)(w * qi[s]);
            off[i*4 + s] = (ih * ds[s] + iw) * Cs[s];
        }
    }
    int4* dst = reinterpret_cast<int4*>(g_off + p*12);
    dst[0] = make_int4(off[0], off[1], off[2],  off[3]);
    dst[1] = make_int4(off[4], off[5], off[6],  off[7]);
    dst[2] = make_int4(off[8], off[9], off[10], off[11]);
}

// --- kernel B: float4 gather + stats into smem, then coalesced aligned write
__global__ __launch_bounds__(256)
void gather_kernel(const float* __restrict__ f1, const float* __restrict__ f2,
                   const float* __restrict__ f3, const float* __restrict__ f4,
                   const float* __restrict__ coord, float* __restrict__ out) {
    int p = blockIdx.x;
    int t = threadIdx.x;

    __shared__ int   soff[12];
    __shared__ float sbuf[OUT_STRIDE + 1];   // full output row staged here

    if (t < 12) soff[t] = g_off[p*12 + t];
    else if (t >= 16 && t < 19) sbuf[t - 16] = __ldg(coord + p*3 + (t - 16));
    __syncthreads();

    if (t < 240) {
        int c4 = t * 4;               // first of 4 consecutive channels
        const float* f;
        int cl, s;
        if (c4 < 64)       { s = 0; f = f1; cl = c4; }
        else if (c4 < 192) { s = 1; f = f2; cl = c4 - 64; }
        else if (c4 < 448) { s = 2; f = f3; cl = c4 - 192; }
        else               { s = 3; f = f4; cl = c4 - 448; }

        float4 a = __ldg(reinterpret_cast<const float4*>(f + soff[0 + s] + cl));
        float4 b = __ldg(reinterpret_cast<const float4*>(f + soff[4 + s] + cl));
        float4 d = __ldg(reinterpret_cast<const float4*>(f + soff[8 + s] + cl));

        float av[4] = { a.x, a.y, a.z, a.w };
        float bv[4] = { b.x, b.y, b.z, b.w };
        float dv[4] = { d.x, d.y, d.z, d.w };

        #pragma unroll
        for (int k = 0; k < 4; k++) {
            float aa = av[k], bb = bv[k], dd = dv[k];
            float mx = fmaxf(aa, fmaxf(bb, dd));
            float mn = (aa + bb + dd) * (1.0f / 3.0f);
            float da = aa - mn, db = bb - mn, dc = dd - mn;
            float sd = sqrtf((da*da + db*db + dc*dc) * (1.0f / 3.0f));
            sbuf[3 + c4 + k]    = mx;
            sbuf[963 + c4 + k]  = mn;
            sbuf[1923 + c4 + k] = sd;
        }
    }
    __syncthreads();

    // Coalesced, 16B-aligned writeback of the full row.
    size_t g = (size_t)p * OUT_STRIDE;
    int lead = (int)((4 - (g & 3)) & 3);          // scalars to reach 16B align
    if (t < lead) out[g + t] = sbuf[t];

    int nvec = (OUT_STRIDE - lead) >> 2;          // 719 or 720 float4s
    float* ob = out + g + lead;
    const float* sb = sbuf + lead;
    #pragma unroll
    for (int i = t; i < nvec; i += 256) {
        int j = i * 4;
        float4 v = make_float4(sb[j], sb[j+1], sb[j+2], sb[j+3]);
        *reinterpret_cast<float4*>(ob + j) = v;
    }

    int done = lead + (nvec << 2);
    int tail = OUT_STRIDE - done;                 // 0..3 scalars
    if (t >= 8 && t < 8 + tail) out[g + done + (t - 8)] = sbuf[done + (t - 8)];
}

extern "C" void kernel_launch(void* const* d_in, const int* in_sizes, int n_in,
                              void* d_out, int out_size) {
    const float* coord = (const float*)d_in[0];
    const float* cams  = (const float*)d_in[1];
    const float* f1    = (const float*)d_in[2];
    const float* f2    = (const float*)d_in[3];
    const float* f3    = (const float*)d_in[4];
    const float* f4    = (const float*)d_in[5];
    float* out = (float*)d_out;

    int N = in_sizes[0] / 3;

    proj_kernel<<<(N + 255) / 256, 256>>>(coord, cams, N);
    gather_kernel<<<N, 256>>>(f1, f2, f3, f4, coord, out);
}

// round 4
// speedup vs baseline: 2.2057x; 1.3708x over previous
#include <cuda_runtime.h>
#include <math.h>
#include <stdint.h>

// ---------------------------------------------------------------------------
// GraphProjection: 80000 points, 3 cameras, feature pyramid (64/128/256/512 ch)
// out[p] = [coord(3) | max over views(960) | mean(960) | std(960)] -> 2883 f32
// Round 4: conflict-free smem staging (aligned STS.128, element e at sbuf[1+e])
//          + scalar-coalesced writeback (lane-consecutive LDS/STG).
// ---------------------------------------------------------------------------

#define MAX_N 80000
#define OUT_STRIDE 2883

__device__ int g_off[MAX_N * 12];   // [point][view*4 + scale] flat float offset

struct CamData {
    float B0[9];     // inv(c0^T)
    float c[3][9];   // per-view rotation rows (X,Y,Z normalized)
    float o[3][3];   // per-view camera origin (unnormalized Z)
};

// --- camera matrix, mirroring jnp fp32 op order -----------------------------
__device__ __forceinline__ void cam_mat(const float* prm, float* Crow, float* O) {
    const float PI = 3.14159265358979323846f;
    float theta = prm[0] * PI / 180.0f;
    float e     = prm[1] * PI / 180.0f;
    float camy  = prm[3] * sinf(e);
    float lens  = prm[3] * cosf(e);
    float camx  = lens * cosf(theta);
    float camz  = lens * sinf(theta);

    float Zv[3] = { camx, camy, camz };
    float Yv[3] = { camy * cosf(theta + PI), lens, camy * sinf(theta + PI) };
    float Xv[3] = { Yv[1]*Zv[2] - Yv[2]*Zv[1],
                    Yv[2]*Zv[0] - Yv[0]*Zv[2],
                    Yv[0]*Zv[1] - Yv[1]*Zv[0] };

    float nx = sqrtf(Xv[0]*Xv[0] + Xv[1]*Xv[1] + Xv[2]*Xv[2]);
    float ny = sqrtf(Yv[0]*Yv[0] + Yv[1]*Yv[1] + Yv[2]*Yv[2]);
    float nz = sqrtf(Zv[0]*Zv[0] + Zv[1]*Zv[1] + Zv[2]*Zv[2]);
    for (int k = 0; k < 3; k++) {
        Crow[0*3 + k] = __fdiv_rn(Xv[k], nx);
        Crow[1*3 + k] = __fdiv_rn(Yv[k], ny);
        Crow[2*3 + k] = __fdiv_rn(Zv[k], nz);
        O[k] = Zv[k];
    }
}

// --- kernel A: per-block camera setup (incl. DP inverse) + per-point offsets
__global__ __launch_bounds__(256)
void proj_kernel(const float* __restrict__ coord,
                 const float* __restrict__ cams, int N) {
    __shared__ CamData cam;

    if (threadIdx.x == 0) {
        for (int i = 0; i < 3; i++)
            cam_mat(cams + i * 5, cam.c[i], cam.o[i]);

        double M[3][3];
        for (int r = 0; r < 3; r++)
            for (int k = 0; k < 3; k++)
                M[r][k] = (double)cam.c[0][k*3 + r];

        double det = M[0][0]*(M[1][1]*M[2][2] - M[1][2]*M[2][1])
                   - M[0][1]*(M[1][0]*M[2][2] - M[1][2]*M[2][0])
                   + M[0][2]*(M[1][0]*M[2][1] - M[1][1]*M[2][0]);
        double inv[3][3];
        inv[0][0] =  (M[1][1]*M[2][2] - M[1][2]*M[2][1]) / det;
        inv[0][1] =  (M[0][2]*M[2][1] - M[0][1]*M[2][2]) / det;
        inv[0][2] =  (M[0][1]*M[1][2] - M[0][2]*M[1][1]) / det;
        inv[1][0] =  (M[1][2]*M[2][0] - M[1][0]*M[2][2]) / det;
        inv[1][1] =  (M[0][0]*M[2][2] - M[0][2]*M[2][0]) / det;
        inv[1][2] =  (M[0][2]*M[1][0] - M[0][0]*M[1][2]) / det;
        inv[2][0] =  (M[1][0]*M[2][1] - M[1][1]*M[2][0]) / det;
        inv[2][1] =  (M[0][1]*M[2][0] - M[0][0]*M[2][1]) / det;
        inv[2][2] =  (M[0][0]*M[1][1] - M[0][1]*M[1][0]) / det;
        for (int k = 0; k < 3; k++)
            for (int j = 0; j < 3; j++)
                cam.B0[k*3 + j] = (float)inv[k][j];
    }
    __syncthreads();

    int p = blockIdx.x * blockDim.x + threadIdx.x;
    if (p >= N) return;

    float x = coord[p*3 + 0];
    float y = coord[p*3 + 1];
    float z = coord[p*3 + 2];

    float po[3];
    #pragma unroll
    for (int j = 0; j < 3; j++)
        po[j] = x * cam.B0[0*3 + j] + y * cam.B0[1*3 + j]
              + z * cam.B0[2*3 + j] + cam.o[0][j];

    const int   ds[4] = { 56, 28, 14, 7 };
    const int   Cs[4] = { 64, 128, 256, 512 };
    const float qi[4] = { 0.25f, 0.125f, 0.0625f, 0.03125f };  // d/224 exact pow2

    int off[12];
    #pragma unroll
    for (int i = 0; i < 3; i++) {
        float vx = po[0] - cam.o[i][0];
        float vy = po[1] - cam.o[i][1];
        float vz = po[2] - cam.o[i][2];
        const float* C = cam.c[i];
        float X  = vx*C[0] + vy*C[1] + vz*C[2];
        float Y  = vx*C[3] + vy*C[4] + vz*C[5];
        float Zc = vx*C[6] + vy*C[7] + vz*C[8];

        float negz = -Zc;
        float h = __fdiv_rn(248.0f * (-Y), negz) + 112.0f;
        float w = __fdiv_rn(248.0f * X,    negz) + 112.0f;
        h = fminf(fmaxf(h, 0.0f), 223.0f);
        w = fminf(fmaxf(w, 0.0f), 223.0f);

        #pragma unroll
        for (int s = 0; s < 4; s++) {
            int ih = (int)(h * qi[s]);
            int iw = (int)(w * qi[s]);
            off[i*4 + s] = (ih * ds[s] + iw) * Cs[s];
        }
    }
    int4* dst = reinterpret_cast<int4*>(g_off + p*12);
    dst[0] = make_int4(off[0], off[1], off[2],  off[3]);
    dst[1] = make_int4(off[4], off[5], off[6],  off[7]);
    dst[2] = make_int4(off[8], off[9], off[10], off[11]);
}

// --- kernel B: float4 gather + stats -> aligned STS.128 staging,
//     then scalar-coalesced (conflict-free) writeback.
__global__ __launch_bounds__(256)
void gather_kernel(const float* __restrict__ f1, const float* __restrict__ f2,
                   const float* __restrict__ f3, const float* __restrict__ f4,
                   const float* __restrict__ coord, float* __restrict__ out) {
    int p = blockIdx.x;
    int t = threadIdx.x;

    __shared__ int soff[12];
    // element e of the output row lives at sbuf[1+e]:
    //   coord -> sbuf[1..3]
    //   mx    -> sbuf[4 + c]     (4    % 4 == 0: STS.128-aligned)
    //   mn    -> sbuf[964 + c]   (964  % 4 == 0)
    //   sd    -> sbuf[1924 + c]  (1924 % 4 == 0)
    __shared__ __align__(16) float sbuf[OUT_STRIDE + 1];

    if (t < 12) soff[t] = g_off[p*12 + t];
    __syncthreads();

    if (t < 240) {
        int c4 = t * 4;               // first of 4 consecutive channels
        const float* f;
        int cl, s;
        if (c4 < 64)       { s = 0; f = f1; cl = c4; }
        else if (c4 < 192) { s = 1; f = f2; cl = c4 - 64; }
        else if (c4 < 448) { s = 2; f = f3; cl = c4 - 192; }
        else               { s = 3; f = f4; cl = c4 - 448; }

        float4 a = __ldg(reinterpret_cast<const float4*>(f + soff[0 + s] + cl));
        float4 b = __ldg(reinterpret_cast<const float4*>(f + soff[4 + s] + cl));
        float4 d = __ldg(reinterpret_cast<const float4*>(f + soff[8 + s] + cl));

        float av[4] = { a.x, a.y, a.z, a.w };
        float bv[4] = { b.x, b.y, b.z, b.w };
        float dv[4] = { d.x, d.y, d.z, d.w };

        float mxv[4], mnv[4], sdv[4];
        #pragma unroll
        for (int k = 0; k < 4; k++) {
            float aa = av[k], bb = bv[k], dd = dv[k];
            mxv[k] = fmaxf(aa, fmaxf(bb, dd));
            float mn = (aa + bb + dd) * (1.0f / 3.0f);
            mnv[k] = mn;
            float da = aa - mn, db = bb - mn, dc = dd - mn;
            sdv[k] = sqrtf((da*da + db*db + dc*dc) * (1.0f / 3.0f));
        }
        // aligned, conflict-free STS.128
        *reinterpret_cast<float4*>(sbuf + 4 + c4)    = make_float4(mxv[0], mxv[1], mxv[2], mxv[3]);
        *reinterpret_cast<float4*>(sbuf + 964 + c4)  = make_float4(mnv[0], mnv[1], mnv[2], mnv[3]);
        *reinterpret_cast<float4*>(sbuf + 1924 + c4) = make_float4(sdv[0], sdv[1], sdv[2], sdv[3]);
    } else if (t < 243) {
        sbuf[1 + (t - 240)] = __ldg(coord + p*3 + (t - 240));
    }
    __syncthreads();

    // scalar-coalesced writeback: lane-consecutive LDS (conflict-free) + STG
    size_t g = (size_t)p * OUT_STRIDE;
    #pragma unroll 4
    for (int e = t; e < OUT_STRIDE; e += 256)
        out[g + e] = sbuf[1 + e];
}

extern "C" void kernel_launch(void* const* d_in, const int* in_sizes, int n_in,
                              void* d_out, int out_size) {
    const float* coord = (const float*)d_in[0];
    const float* cams  = (const float*)d_in[1];
    const float* f1    = (const float*)d_in[2];
    const float* f2    = (const float*)d_in[3];
    const float* f3    = (const float*)d_in[4];
    const float* f4    = (const float*)d_in[5];
    float* out = (float*)d_out;

    int N = in_sizes[0] / 3;

    proj_kernel<<<(N + 255) / 256, 256>>>(coord, cams, N);
    gather_kernel<<<N, 256>>>(f1, f2, f3, f4, coord, out);
}

// round 5
// speedup vs baseline: 2.3234x; 1.0534x over previous
#include <cuda_runtime.h>
#include <math.h>
#include <stdint.h>

// ---------------------------------------------------------------------------
// GraphProjection: 80000 points, 3 cameras, feature pyramid (64/128/256/512 ch)
// out[p] = [coord(3) | max over views(960) | mean(960) | std(960)] -> 2883 f32
// Round 5: writeback body 128B-aligned in GLOBAL (head scalars first) so every
//          body store-warp hits exactly one L1 line. Gather/STS/LDS unchanged
//          (already at byte-minimum wavefronts).
// ---------------------------------------------------------------------------

#define MAX_N 80000
#define OUT_STRIDE 2883

__device__ int g_off[MAX_N * 12];   // [point][view*4 + scale] flat float offset

struct CamData {
    float B0[9];     // inv(c0^T)
    float c[3][9];   // per-view rotation rows (X,Y,Z normalized)
    float o[3][3];   // per-view camera origin (unnormalized Z)
};

// --- camera matrix, mirroring jnp fp32 op order -----------------------------
__device__ __forceinline__ void cam_mat(const float* prm, float* Crow, float* O) {
    const float PI = 3.14159265358979323846f;
    float theta = prm[0] * PI / 180.0f;
    float e     = prm[1] * PI / 180.0f;
    float camy  = prm[3] * sinf(e);
    float lens  = prm[3] * cosf(e);
    float camx  = lens * cosf(theta);
    float camz  = lens * sinf(theta);

    float Zv[3] = { camx, camy, camz };
    float Yv[3] = { camy * cosf(theta + PI), lens, camy * sinf(theta + PI) };
    float Xv[3] = { Yv[1]*Zv[2] - Yv[2]*Zv[1],
                    Yv[2]*Zv[0] - Yv[0]*Zv[2],
                    Yv[0]*Zv[1] - Yv[1]*Zv[0] };

    float nx = sqrtf(Xv[0]*Xv[0] + Xv[1]*Xv[1] + Xv[2]*Xv[2]);
    float ny = sqrtf(Yv[0]*Yv[0] + Yv[1]*Yv[1] + Yv[2]*Yv[2]);
    float nz = sqrtf(Zv[0]*Zv[0] + Zv[1]*Zv[1] + Zv[2]*Zv[2]);
    for (int k = 0; k < 3; k++) {
        Crow[0*3 + k] = __fdiv_rn(Xv[k], nx);
        Crow[1*3 + k] = __fdiv_rn(Yv[k], ny);
        Crow[2*3 + k] = __fdiv_rn(Zv[k], nz);
        O[k] = Zv[k];
    }
}

// --- kernel A: per-block camera setup (incl. DP inverse) + per-point offsets
__global__ __launch_bounds__(256)
void proj_kernel(const float* __restrict__ coord,
                 const float* __restrict__ cams, int N) {
    __shared__ CamData cam;

    if (threadIdx.x == 0) {
        for (int i = 0; i < 3; i++)
            cam_mat(cams + i * 5, cam.c[i], cam.o[i]);

        double M[3][3];
        for (int r = 0; r < 3; r++)
            for (int k = 0; k < 3; k++)
                M[r][k] = (double)cam.c[0][k*3 + r];

        double det = M[0][0]*(M[1][1]*M[2][2] - M[1][2]*M[2][1])
                   - M[0][1]*(M[1][0]*M[2][2] - M[1][2]*M[2][0])
                   + M[0][2]*(M[1][0]*M[2][1] - M[1][1]*M[2][0]);
        double inv[3][3];
        inv[0][0] =  (M[1][1]*M[2][2] - M[1][2]*M[2][1]) / det;
        inv[0][1] =  (M[0][2]*M[2][1] - M[0][1]*M[2][2]) / det;
        inv[0][2] =  (M[0][1]*M[1][2] - M[0][2]*M[1][1]) / det;
        inv[1][0] =  (M[1][2]*M[2][0] - M[1][0]*M[2][2]) / det;
        inv[1][1] =  (M[0][0]*M[2][2] - M[0][2]*M[2][0]) / det;
        inv[1][2] =  (M[0][2]*M[1][0] - M[0][0]*M[1][2]) / det;
        inv[2][0] =  (M[1][0]*M[2][1] - M[1][1]*M[2][0]) / det;
        inv[2][1] =  (M[0][1]*M[2][0] - M[0][0]*M[2][1]) / det;
        inv[2][2] =  (M[0][0]*M[1][1] - M[0][1]*M[1][0]) / det;
        for (int k = 0; k < 3; k++)
            for (int j = 0; j < 3; j++)
                cam.B0[k*3 + j] = (float)inv[k][j];
    }
    __syncthreads();

    int p = blockIdx.x * blockDim.x + threadIdx.x;
    if (p >= N) return;

    float x = coord[p*3 + 0];
    float y = coord[p*3 + 1];
    float z = coord[p*3 + 2];

    float po[3];
    #pragma unroll
    for (int j = 0; j < 3; j++)
        po[j] = x * cam.B0[0*3 + j] + y * cam.B0[1*3 + j]
              + z * cam.B0[2*3 + j] + cam.o[0][j];

    const int   ds[4] = { 56, 28, 14, 7 };
    const int   Cs[4] = { 64, 128, 256, 512 };
    const float qi[4] = { 0.25f, 0.125f, 0.0625f, 0.03125f };  // d/224 exact pow2

    int off[12];
    #pragma unroll
    for (int i = 0; i < 3; i++) {
        float vx = po[0] - cam.o[i][0];
        float vy = po[1] - cam.o[i][1];
        float vz = po[2] - cam.o[i][2];
        const float* C = cam.c[i];
        float X  = vx*C[0] + vy*C[1] + vz*C[2];
        float Y  = vx*C[3] + vy*C[4] + vz*C[5];
        float Zc = vx*C[6] + vy*C[7] + vz*C[8];

        float negz = -Zc;
        float h = __fdiv_rn(248.0f * (-Y), negz) + 112.0f;
        float w = __fdiv_rn(248.0f * X,    negz) + 112.0f;
        h = fminf(fmaxf(h, 0.0f), 223.0f);
        w = fminf(fmaxf(w, 0.0f), 223.0f);

        #pragma unroll
        for (int s = 0; s < 4; s++) {
            int ih = (int)(h * qi[s]);
            int iw = (int)(w * qi[s]);
            off[i*4 + s] = (ih * ds[s] + iw) * Cs[s];
        }
    }
    int4* dst = reinterpret_cast<int4*>(g_off + p*12);
    dst[0] = make_int4(off[0], off[1], off[2],  off[3]);
    dst[1] = make_int4(off[4], off[5], off[6],  off[7]);
    dst[2] = make_int4(off[8], off[9], off[10], off[11]);
}

// --- kernel B: float4 gather + stats -> aligned STS.128 staging,
//     then writeback with 128B-global-aligned body (1 L1 line per store-warp).
__global__ __launch_bounds__(256)
void gather_kernel(const float* __restrict__ f1, const float* __restrict__ f2,
                   const float* __restrict__ f3, const float* __restrict__ f4,
                   const float* __restrict__ coord, float* __restrict__ out) {
    int p = blockIdx.x;
    int t = threadIdx.x;

    __shared__ int soff[12];
    // element e of the output row lives at sbuf[1+e]:
    //   coord -> sbuf[1..3]; mx -> sbuf[4+c]; mn -> sbuf[964+c]; sd -> sbuf[1924+c]
    __shared__ __align__(16) float sbuf[OUT_STRIDE + 1];

    if (t < 12) soff[t] = g_off[p*12 + t];
    __syncthreads();

    if (t < 240) {
        int c4 = t * 4;               // first of 4 consecutive channels
        const float* f;
        int cl, s;
        if (c4 < 64)       { s = 0; f = f1; cl = c4; }
        else if (c4 < 192) { s = 1; f = f2; cl = c4 - 64; }
        else if (c4 < 448) { s = 2; f = f3; cl = c4 - 192; }
        else               { s = 3; f = f4; cl = c4 - 448; }

        float4 a = __ldg(reinterpret_cast<const float4*>(f + soff[0 + s] + cl));
        float4 b = __ldg(reinterpret_cast<const float4*>(f + soff[4 + s] + cl));
        float4 d = __ldg(reinterpret_cast<const float4*>(f + soff[8 + s] + cl));

        float av[4] = { a.x, a.y, a.z, a.w };
        float bv[4] = { b.x, b.y, b.z, b.w };
        float dv[4] = { d.x, d.y, d.z, d.w };

        float mxv[4], mnv[4], sdv[4];
        #pragma unroll
        for (int k = 0; k < 4; k++) {
            float aa = av[k], bb = bv[k], dd = dv[k];
            mxv[k] = fmaxf(aa, fmaxf(bb, dd));
            float mn = (aa + bb + dd) * (1.0f / 3.0f);
            mnv[k] = mn;
            float da = aa - mn, db = bb - mn, dc = dd - mn;
            sdv[k] = sqrtf((da*da + db*db + dc*dc) * (1.0f / 3.0f));
        }
        // aligned, conflict-free STS.128
        *reinterpret_cast<float4*>(sbuf + 4 + c4)    = make_float4(mxv[0], mxv[1], mxv[2], mxv[3]);
        *reinterpret_cast<float4*>(sbuf + 964 + c4)  = make_float4(mnv[0], mnv[1], mnv[2], mnv[3]);
        *reinterpret_cast<float4*>(sbuf + 1924 + c4) = make_float4(sdv[0], sdv[1], sdv[2], sdv[3]);
    } else if (t < 243) {
        sbuf[1 + (t - 240)] = __ldg(coord + p*3 + (t - 240));
    }
    __syncthreads();

    // Writeback: head scalars up to the next 128B global boundary, then a body
    // where every warp's 32 consecutive stores cover exactly one 128B line.
    size_t g = (size_t)p * OUT_STRIDE;
    int head = (int)((32 - (g & 31)) & 31);     // elements to 128B boundary
    if (t < head) out[g + t] = sbuf[1 + t];

    #pragma unroll 4
    for (int e = head + t; e < OUT_STRIDE; e += 256)
        out[g + e] = sbuf[1 + e];
}

extern "C" void kernel_launch(void* const* d_in, const int* in_sizes, int n_in,
                              void* d_out, int out_size) {
    const float* coord = (const float*)d_in[0];
    const float* cams  = (const float*)d_in[1];
    const float* f1    = (const float*)d_in[2];
    const float* f2    = (const float*)d_in[3];
    const float* f3    = (const float*)d_in[4];
    const float* f4    = (const float*)d_in[5];
    float* out = (float*)d_out;

    int N = in_sizes[0] / 3;

    proj_kernel<<<(N + 255) / 256, 256>>>(coord, cams, N);
    gather_kernel<<<N, 256>>>(f1, f2, f3, f4, coord, out);
}

// round 6
// speedup vs baseline: 2.3781x; 1.0235x over previous
#include <cuda_runtime.h>
#include <math.h>
#include <stdint.h>

// ---------------------------------------------------------------------------
// GraphProjection: 80000 points, 3 cameras, feature pyramid (64/128/256/512 ch)
// out[p] = [coord(3) | max over views(960) | mean(960) | std(960)] -> 2883 f32
// Round 6: no smem staging. warp -> 32-channel row, lane -> channel.
//   loads : 3 scalar LDG per row, lane-consecutive, 256B-aligned (1 wf each)
//   stores: 3 scalar STG per row, lane-consecutive direct to out (2 wf each)
//   271 wf/point (vs 362) and ~40% fewer issued instructions (no STS/LDS loop).
// ---------------------------------------------------------------------------

#define MAX_N 80000
#define OUT_STRIDE 2883

__device__ int g_off[MAX_N * 12];   // [point][view*4 + scale] flat float offset

struct CamData {
    float B0[9];     // inv(c0^T)
    float c[3][9];   // per-view rotation rows (X,Y,Z normalized)
    float o[3][3];   // per-view camera origin (unnormalized Z)
};

// --- camera matrix, mirroring jnp fp32 op order -----------------------------
__device__ __forceinline__ void cam_mat(const float* prm, float* Crow, float* O) {
    const float PI = 3.14159265358979323846f;
    float theta = prm[0] * PI / 180.0f;
    float e     = prm[1] * PI / 180.0f;
    float camy  = prm[3] * sinf(e);
    float lens  = prm[3] * cosf(e);
    float camx  = lens * cosf(theta);
    float camz  = lens * sinf(theta);

    float Zv[3] = { camx, camy, camz };
    float Yv[3] = { camy * cosf(theta + PI), lens, camy * sinf(theta + PI) };
    float Xv[3] = { Yv[1]*Zv[2] - Yv[2]*Zv[1],
                    Yv[2]*Zv[0] - Yv[0]*Zv[2],
                    Yv[0]*Zv[1] - Yv[1]*Zv[0] };

    float nx = sqrtf(Xv[0]*Xv[0] + Xv[1]*Xv[1] + Xv[2]*Xv[2]);
    float ny = sqrtf(Yv[0]*Yv[0] + Yv[1]*Yv[1] + Yv[2]*Yv[2]);
    float nz = sqrtf(Zv[0]*Zv[0] + Zv[1]*Zv[1] + Zv[2]*Zv[2]);
    for (int k = 0; k < 3; k++) {
        Crow[0*3 + k] = __fdiv_rn(Xv[k], nx);
        Crow[1*3 + k] = __fdiv_rn(Yv[k], ny);
        Crow[2*3 + k] = __fdiv_rn(Zv[k], nz);
        O[k] = Zv[k];
    }
}

// --- kernel A: per-block camera setup (incl. DP inverse) + per-point offsets
__global__ __launch_bounds__(256)
void proj_kernel(const float* __restrict__ coord,
                 const float* __restrict__ cams, int N) {
    __shared__ CamData cam;

    if (threadIdx.x == 0) {
        for (int i = 0; i < 3; i++)
            cam_mat(cams + i * 5, cam.c[i], cam.o[i]);

        double M[3][3];
        for (int r = 0; r < 3; r++)
            for (int k = 0; k < 3; k++)
                M[r][k] = (double)cam.c[0][k*3 + r];

        double det = M[0][0]*(M[1][1]*M[2][2] - M[1][2]*M[2][1])
                   - M[0][1]*(M[1][0]*M[2][2] - M[1][2]*M[2][0])
                   + M[0][2]*(M[1][0]*M[2][1] - M[1][1]*M[2][0]);
        double inv[3][3];
        inv[0][0] =  (M[1][1]*M[2][2] - M[1][2]*M[2][1]) / det;
        inv[0][1] =  (M[0][2]*M[2][1] - M[0][1]*M[2][2]) / det;
        inv[0][2] =  (M[0][1]*M[1][2] - M[0][2]*M[1][1]) / det;
        inv[1][0] =  (M[1][2]*M[2][0] - M[1][0]*M[2][2]) / det;
        inv[1][1] =  (M[0][0]*M[2][2] - M[0][2]*M[2][0]) / det;
        inv[1][2] =  (M[0][2]*M[1][0] - M[0][0]*M[1][2]) / det;
        inv[2][0] =  (M[1][0]*M[2][1] - M[1][1]*M[2][0]) / det;
        inv[2][1] =  (M[0][1]*M[2][0] - M[0][0]*M[2][1]) / det;
        inv[2][2] =  (M[0][0]*M[1][1] - M[0][1]*M[1][0]) / det;
        for (int k = 0; k < 3; k++)
            for (int j = 0; j < 3; j++)
                cam.B0[k*3 + j] = (float)inv[k][j];
    }
    __syncthreads();

    int p = blockIdx.x * blockDim.x + threadIdx.x;
    if (p >= N) return;

    float x = coord[p*3 + 0];
    float y = coord[p*3 + 1];
    float z = coord[p*3 + 2];

    float po[3];
    #pragma unroll
    for (int j = 0; j < 3; j++)
        po[j] = x * cam.B0[0*3 + j] + y * cam.B0[1*3 + j]
              + z * cam.B0[2*3 + j] + cam.o[0][j];

    const int   ds[4] = { 56, 28, 14, 7 };
    const int   Cs[4] = { 64, 128, 256, 512 };
    const float qi[4] = { 0.25f, 0.125f, 0.0625f, 0.03125f };  // d/224 exact pow2

    int off[12];
    #pragma unroll
    for (int i = 0; i < 3; i++) {
        float vx = po[0] - cam.o[i][0];
        float vy = po[1] - cam.o[i][1];
        float vz = po[2] - cam.o[i][2];
        const float* C = cam.c[i];
        float X  = vx*C[0] + vy*C[1] + vz*C[2];
        float Y  = vx*C[3] + vy*C[4] + vz*C[5];
        float Zc = vx*C[6] + vy*C[7] + vz*C[8];

        float negz = -Zc;
        float h = __fdiv_rn(248.0f * (-Y), negz) + 112.0f;
        float w = __fdiv_rn(248.0f * X,    negz) + 112.0f;
        h = fminf(fmaxf(h, 0.0f), 223.0f);
        w = fminf(fmaxf(w, 0.0f), 223.0f);

        #pragma unroll
        for (int s = 0; s < 4; s++) {
            int ih = (int)(h * qi[s]);
            int iw = (int)(w * qi[s]);
            off[i*4 + s] = (ih * ds[s] + iw) * Cs[s];
        }
    }
    int4* dst = reinterpret_cast<int4*>(g_off + p*12);
    dst[0] = make_int4(off[0], off[1], off[2],  off[3]);
    dst[1] = make_int4(off[4], off[5], off[6],  off[7]);
    dst[2] = make_int4(off[8], off[9], off[10], off[11]);
}

// --- kernel B: row-mapped gather + stats, direct stores (no smem staging) ---
__global__ __launch_bounds__(256)
void gather_kernel(const float* __restrict__ f1, const float* __restrict__ f2,
                   const float* __restrict__ f3, const float* __restrict__ f4,
                   const float* __restrict__ coord, float* __restrict__ out) {
    int p    = blockIdx.x;
    int t    = threadIdx.x;
    int wid  = t >> 5;
    int lane = t & 31;

    __shared__ int soff[12];
    if (t < 12) soff[t] = g_off[p*12 + t];
    __syncthreads();

    size_t g = (size_t)p * OUT_STRIDE;
    if (t >= 32 && t < 35)                 // warp 1: coord passthrough
        out[g + (t - 32)] = __ldg(coord + p*3 + (t - 32));

    // 30 channel-rows of 32; warp w handles rows w, w+8, w+16, w+24.
    #pragma unroll
    for (int i = 0; i < 4; i++) {
        int r = wid + (i << 3);
        if (r >= 30) break;
        int c = (r << 5) + lane;

        const float* f;
        int base, s;
        if (c < 64)       { s = 0; f = f1; base = 0; }
        else if (c < 192) { s = 1; f = f2; base = 64; }
        else if (c < 448) { s = 2; f = f3; base = 192; }
        else              { s = 3; f = f4; base = 448; }
        int cl = c - base;

        float a = __ldg(f + soff[0 + s] + cl);
        float b = __ldg(f + soff[4 + s] + cl);
        float d = __ldg(f + soff[8 + s] + cl);

        float mx = fmaxf(a, fmaxf(b, d));
        float mn = (a + b + d) * (1.0f / 3.0f);
        float da = a - mn, db = b - mn, dc = d - mn;
        float sd = sqrtf((da*da + db*db + dc*dc) * (1.0f / 3.0f));

        out[g + 3 + c]    = mx;
        out[g + 963 + c]  = mn;
        out[g + 1923 + c] = sd;
    }
}

extern "C" void kernel_launch(void* const* d_in, const int* in_sizes, int n_in,
                              void* d_out, int out_size) {
    const float* coord = (const float*)d_in[0];
    const float* cams  = (const float*)d_in[1];
    const float* f1    = (const float*)d_in[2];
    const float* f2    = (const float*)d_in[3];
    const float* f3    = (const float*)d_in[4];
    const float* f4    = (const float*)d_in[5];
    float* out = (float*)d_out;

    int N = in_sizes[0] / 3;

    proj_kernel<<<(N + 255) / 256, 256>>>(coord, cams, N);
    gather_kernel<<<N, 256>>>(f1, f2, f3, f4, coord, out);
}